// round 13
// baseline (speedup 1.0000x reference)
#include <cuda_runtime.h>
#include <cuda_fp16.h>
#include <cuda_fp8.h>
#include <stdint.h>

// ---------------- problem constants ----------------
#define BB 8192
#define HH 1024
#define LL 1024
#define NHEAD 5

// ---------------- GEMM config ----------------
#define TM 128
#define TN 128
#define KC 64            // K bytes per smem chunk
#define NC (HH / KC)     // 16 chunks
#define NSTAGE 5
#define NTHREADS 160     // 4 consumer warps (64x64 tiles) + 1 producer warp

#define WSCALE 64.0f
#define INV_WSCALE (1.0f / 64.0f)

// smem: rowIdx 512B | barriers (full/empty interleaved, 16B/stage) | 5 stages of (A 8K | B 8K)
#define SM_BAR 512
#define STAGE_BYTES (128 * 64 + 128 * 64)
#define SM_STAGE0 1024
#define SMEM_TOTAL (SM_STAGE0 + NSTAGE * STAGE_BYTES)

// prep kernel block ranges: block 0 = bucket; then A-convert; then W-convert
#define PREP_A_BLOCKS 1024                   // 8 warps/block -> 8192 rows
#define PREP_W_BLOCKS 1280                   // 5M elems / 16 / 256
#define PREP_BLOCKS (1 + PREP_A_BLOCKS + PREP_W_BLOCKS)

// ---------------- scratch ----------------
__device__ int g_cnt[8];
__device__ int g_rows[6 * BB];
__device__ uint8_t g_a8[(size_t)BB * HH];                // e4m3 hidden (natural order)
__device__ uint8_t g_w8[(size_t)NHEAD * LL * HH];        // e4m3 W * 64

// ---------------- PTX helpers ----------------
__device__ __forceinline__ uint32_t smem_u32(const void* p) {
    uint32_t a;
    asm("{ .reg .u64 t; cvta.to.shared.u64 t, %1; cvt.u32.u64 %0, t; }" : "=r"(a) : "l"(p));
    return a;
}
#define CP_ASYNC16(dst, src) \
    asm volatile("cp.async.cg.shared.global [%0], [%1], 16;" :: "r"(dst), "l"(src))
#define CP_MBAR_ARRIVE(bar) \
    asm volatile("cp.async.mbarrier.arrive.noinc.shared.b64 [%0];" :: "r"(bar) : "memory")
#define MBARRIER_INIT(addr, cnt) \
    asm volatile("mbarrier.init.shared.b64 [%0], %1;" :: "r"(addr), "r"(cnt) : "memory")
#define MBARRIER_ARRIVE(addr) \
    asm volatile("mbarrier.arrive.shared.b64 _, [%0];" :: "r"(addr) : "memory")
#define MBARRIER_WAIT(addr, parity) do { \
    uint32_t _m = (addr), _p = (parity), _d; \
    asm volatile("{ .reg .pred p; mbarrier.try_wait.parity.shared.b64 p, [%1], %2; selp.b32 %0, 1, 0, p; }" \
        : "=r"(_d) : "r"(_m), "r"(_p) : "memory"); \
    if (!_d) { \
        asm volatile("{ .reg .pred P1; WL%=: mbarrier.try_wait.parity.shared.b64 P1, [%0], %1; @P1 bra.uni WD%=; bra.uni WL%=; WD%=: }" \
            :: "r"(_m), "r"(_p) : "memory"); \
    } } while (0)

// A fragment for m16n8k32 e4m3: lanes 0-15 rows (16B seg c16), lanes 16-31 seg c16+1.
__device__ __forceinline__ void ld_frag4a(uint32_t* f, uint32_t sbase, int rowbase,
                                          int c16, int lane) {
    int r = rowbase + (lane & 15);
    int cc = c16 + (lane >> 4);
    uint32_t addr = sbase + r * 64 + (((cc ^ ((r >> 1) & 3))) << 4);
    asm volatile("ldmatrix.sync.aligned.m8n8.x4.shared.b16 {%0,%1,%2,%3}, [%4];"
                 : "=r"(f[0]), "=r"(f[1]), "=r"(f[2]), "=r"(f[3]) : "r"(addr));
}

// B fragments for two n8 tiles at once.
__device__ __forceinline__ void ld_frag4b(uint32_t* f, uint32_t sbase, int rowbase,
                                          int c16, int lane) {
    int r = rowbase + (lane & 7) + ((lane >> 4) << 3);
    int cc = c16 + ((lane >> 3) & 1);
    uint32_t addr = sbase + r * 64 + (((cc ^ ((r >> 1) & 3))) << 4);
    asm volatile("ldmatrix.sync.aligned.m8n8.x4.shared.b16 {%0,%1,%2,%3}, [%4];"
                 : "=r"(f[0]), "=r"(f[1]), "=r"(f[2]), "=r"(f[3]) : "r"(addr));
}

__device__ __forceinline__ void mma16832(float* d, const uint32_t* a,
                                         uint32_t b0, uint32_t b1) {
    asm volatile(
        "mma.sync.aligned.m16n8k32.row.col.f32.e4m3.e4m3.f32 "
        "{%0,%1,%2,%3}, {%4,%5,%6,%7}, {%8,%9}, {%0,%1,%2,%3};"
        : "+f"(d[0]), "+f"(d[1]), "+f"(d[2]), "+f"(d[3])
        : "r"(a[0]), "r"(a[1]), "r"(a[2]), "r"(a[3]), "r"(b0), "r"(b1));
}

__device__ __forceinline__ uint8_t to_e4m3(float x) {
    return (uint8_t)__nv_cvt_float_to_fp8(x, __NV_SATFINITE, __NV_E4M3);
}
__device__ __forceinline__ uint32_t pack4_e4m3(float4 f) {
    return (uint32_t)to_e4m3(f.x) | ((uint32_t)to_e4m3(f.y) << 8) |
           ((uint32_t)to_e4m3(f.z) << 16) | ((uint32_t)to_e4m3(f.w) << 24);
}

// pack 6 group-counts into two u64 (groups 0-2 / 3-5, 21 bits each)
__device__ __forceinline__ void cnt_add(unsigned long long& c0, unsigned long long& c1,
                                        int g, unsigned long long v) {
    if (g < 3) c0 += v << (g * 21);
    else       c1 += v << ((g - 3) * 21);
}
__device__ __forceinline__ int cnt_get(unsigned long long c0, unsigned long long c1, int g) {
    unsigned long long c = (g < 3) ? c0 : c1;
    int s = ((g < 3) ? g : g - 3) * 21;
    return (int)((c >> s) & 0x1FFFFF);
}

// ---------------- fused prep ----------------
__global__ __launch_bounds__(256)
void prep_kernel(const float* __restrict__ hs, const float* __restrict__ W,
                 const int* __restrict__ group, const int* __restrict__ labels,
                 float* __restrict__ out) {
    const int bx = blockIdx.x;
    if (bx == 0) {
        __shared__ unsigned long long s0[256], s1[256];
        const int t = threadIdx.x;
        unsigned long long c0 = 0, c1 = 0;
        int gr[32];
#pragma unroll
        for (int i = 0; i < 32; i++) {
            int g = group[t * 32 + i];
            g = (g < 0) ? 0 : ((g > 5) ? 5 : g);
            gr[i] = g;
            cnt_add(c0, c1, g, 1ull);
        }
        s0[t] = c0; s1[t] = c1;
        __syncthreads();
        for (int off = 1; off < 256; off <<= 1) {
            unsigned long long a0 = (t >= off) ? s0[t - off] : 0ull;
            unsigned long long a1 = (t >= off) ? s1[t - off] : 0ull;
            __syncthreads();
            s0[t] += a0; s1[t] += a1;
            __syncthreads();
        }
        unsigned long long e0 = (t > 0) ? s0[t - 1] : 0ull;
        unsigned long long e1 = (t > 0) ? s1[t - 1] : 0ull;
        if (t < 6) g_cnt[t] = cnt_get(s0[255], s1[255], t);
        int base[6];
#pragma unroll
        for (int g = 0; g < 6; g++) base[g] = cnt_get(e0, e1, g);
#pragma unroll
        for (int i = 0; i < 32; i++) {
            int g = gr[i];
            g_rows[g * BB + base[g]] = t * 32 + i;
            base[g]++;
        }
    } else if (bx <= PREP_A_BLOCKS) {
        const int row = (bx - 1) * 8 + (threadIdx.x >> 5);
        const int lane = threadIdx.x & 31;
        int g = group[row];
        if (g < 0) g = 0;
        if (g > 5) g = 5;
        if (g == 5) {
            float v = (float)labels[row];
            float4 v4 = make_float4(v, v, v, v);
            float4* dp = reinterpret_cast<float4*>(out + (size_t)row * LL);
#pragma unroll
            for (int i = 0; i < 8; i++) dp[lane + i * 32] = v4;
        } else {
            const float4* src = reinterpret_cast<const float4*>(hs + (size_t)row * HH);
            uint32_t* dp = reinterpret_cast<uint32_t*>(g_a8 + (size_t)row * HH);
#pragma unroll
            for (int i = 0; i < 8; i++) dp[lane + i * 32] = pack4_e4m3(src[lane + i * 32]);
        }
    } else {
        const int i = (bx - 1 - PREP_A_BLOCKS) * 256 + threadIdx.x;   // 16-float group
        const float4* src = reinterpret_cast<const float4*>(W) + (size_t)i * 4;
        float4 f0 = src[0], f1 = src[1], f2 = src[2], f3 = src[3];
        f0.x *= WSCALE; f0.y *= WSCALE; f0.z *= WSCALE; f0.w *= WSCALE;
        f1.x *= WSCALE; f1.y *= WSCALE; f1.z *= WSCALE; f1.w *= WSCALE;
        f2.x *= WSCALE; f2.y *= WSCALE; f2.z *= WSCALE; f2.w *= WSCALE;
        f3.x *= WSCALE; f3.y *= WSCALE; f3.z *= WSCALE; f3.w *= WSCALE;
        uint4 o;
        o.x = pack4_e4m3(f0); o.y = pack4_e4m3(f1);
        o.z = pack4_e4m3(f2); o.w = pack4_e4m3(f3);
        reinterpret_cast<uint4*>(g_w8)[i] = o;
    }
}

// ---------------- FP8 MMA GEMM, warp-specialized ----------------
// grid: (LL/TN=8, BB/TM=64, NHEAD). Early exit if row0 >= bucket count.
// warps 0-3: consumers (64x64 tiles); warp 4: producer (all cp.async).
__global__ __launch_bounds__(NTHREADS, 2)
void gemm_fp8_kernel(const float* __restrict__ bias, float* __restrict__ out) {
    const int head = blockIdx.z;
    const int cnt = g_cnt[head];
    const int row0 = blockIdx.y * TM;
    if (row0 >= cnt) return;
    const int col0 = blockIdx.x * TN;

    extern __shared__ char smem[];
    const uint32_t sb = smem_u32(smem);
    int* rowIdx_s = reinterpret_cast<int*>(smem);

    const int tid = threadIdx.x;
    const int wid = tid >> 5;
    const int lid = tid & 31;

    // barrier addresses: full[s] at SM_BAR + 16s, empty[s] at SM_BAR + 16s + 8
    if (tid == 0) {
#pragma unroll
        for (int s = 0; s < NSTAGE; s++) {
            MBARRIER_INIT(sb + SM_BAR + s * 16, 32);      // full: 32 producer-thread async arrivals
            MBARRIER_INIT(sb + SM_BAR + s * 16 + 8, 4);   // empty: 4 consumer-warp arrivals
        }
    }
    if (tid < TM) {
        int r = row0 + tid;
        rowIdx_s[tid] = (r < cnt) ? g_rows[head * BB + r] : -1;
    }
    __syncthreads();

    const uint8_t* __restrict__ bmat = g_w8 + ((size_t)head * LL + col0) * HH;

    if (wid == 4) {
        // -------- producer warp --------
        const uint8_t* aptr[16];
        int boff[16];
        uint32_t dofA[16], dofB[16];
#pragma unroll
        for (int l = 0; l < 16; l++) {
            const int q = l * 32 + lid;      // 0..511
            const int r = q >> 2;
            const int seg = q & 3;
            int v = rowIdx_s[r];
            v = (v < 0) ? 0 : v;
            aptr[l] = g_a8 + (size_t)v * HH + seg * 16;
            dofA[l] = (uint32_t)(r * 64 + ((seg ^ ((r >> 1) & 3)) << 4));
            boff[l] = r * HH + seg * 16;
            dofB[l] = (uint32_t)(8192 + r * 64 + ((seg ^ ((r >> 1) & 3)) << 4));
        }
        int ps = 0, pp = 1;
        for (int c = 0; c < NC; c++) {
            MBARRIER_WAIT(sb + SM_BAR + ps * 16 + 8, pp);      // stage free?
            const uint32_t sbase = sb + SM_STAGE0 + ps * STAGE_BYTES;
            const int k0 = c * KC;
#pragma unroll
            for (int l = 0; l < 16; l++) CP_ASYNC16(sbase + dofA[l], aptr[l] + k0);
#pragma unroll
            for (int l = 0; l < 16; l++) CP_ASYNC16(sbase + dofB[l], bmat + boff[l] + k0);
            CP_MBAR_ARRIVE(sb + SM_BAR + ps * 16);             // full when this thread's copies land
            if (++ps == NSTAGE) { ps = 0; pp ^= 1; }
        }
    } else {
        // -------- consumer warps --------
        const int WM = (wid & 1) * 64;       // 2 warp-rows of 64
        const int WN = (wid >> 1) * 64;      // 2 warp-cols of 64

        float acc[4][8][4];
#pragma unroll
        for (int i = 0; i < 4; i++)
#pragma unroll
            for (int j = 0; j < 8; j++)
#pragma unroll
                for (int k = 0; k < 4; k++) acc[i][j][k] = 0.0f;

        int cs = 0, cph = 0;
        for (int c = 0; c < NC; c++) {
            MBARRIER_WAIT(sb + SM_BAR + cs * 16, cph);         // data ready?
            const uint32_t sbase = sb + SM_STAGE0 + cs * STAGE_BYTES;
            const uint32_t sA = sbase;
            const uint32_t sB = sbase + 8192;
#pragma unroll
            for (int kt = 0; kt < 2; kt++) {
                const int c16 = kt * 2;
                uint32_t bfr[16];
#pragma unroll
                for (int nb = 0; nb < 4; nb++)
                    ld_frag4b(bfr + nb * 4, sB, WN + nb * 16, c16, lid);
                uint32_t afr[16];
#pragma unroll
                for (int mt = 0; mt < 4; mt++)
                    ld_frag4a(afr + mt * 4, sA, WM + mt * 16, c16, lid);
#pragma unroll
                for (int mt = 0; mt < 4; mt++)
#pragma unroll
                    for (int nb = 0; nb < 4; nb++) {
                        mma16832(acc[mt][nb * 2 + 0], afr + mt * 4,
                                 bfr[nb * 4 + 0], bfr[nb * 4 + 1]);
                        mma16832(acc[mt][nb * 2 + 1], afr + mt * 4,
                                 bfr[nb * 4 + 2], bfr[nb * 4 + 3]);
                    }
            }
            if (lid == 0) MBARRIER_ARRIVE(sb + SM_BAR + cs * 16 + 8);   // stage consumed
            if (++cs == NSTAGE) { cs = 0; cph ^= 1; }
        }

        // ---------------- epilogue ----------------
        const int groupID = lid >> 2;
        const int tig = lid & 3;
        const float* brow = bias + head * LL;
#pragma unroll
        for (int mt = 0; mt < 4; mt++) {
            const int mlo = WM + mt * 16 + groupID;
            const int r1 = rowIdx_s[mlo];
            const int r2 = rowIdx_s[mlo + 8];
#pragma unroll
            for (int nt = 0; nt < 8; nt++) {
                const int gc = col0 + WN + nt * 8 + tig * 2;
                const float2 bs = *reinterpret_cast<const float2*>(brow + gc);
                if (r1 >= 0) {
                    float2 v = make_float2(acc[mt][nt][0] * INV_WSCALE + bs.x,
                                           acc[mt][nt][1] * INV_WSCALE + bs.y);
                    *reinterpret_cast<float2*>(out + (size_t)r1 * LL + gc) = v;
                }
                if (r2 >= 0) {
                    float2 v = make_float2(acc[mt][nt][2] * INV_WSCALE + bs.x,
                                           acc[mt][nt][3] * INV_WSCALE + bs.y);
                    *reinterpret_cast<float2*>(out + (size_t)r2 * LL + gc) = v;
                }
            }
        }
    }
}

// ---------------- launch ----------------
extern "C" void kernel_launch(void* const* d_in, const int* in_sizes, int n_in,
                              void* d_out, int out_size) {
    const float* hs     = (const float*)d_in[0];  // [B, H]
    const float* W      = (const float*)d_in[1];  // [5, L, H]
    const float* bias   = (const float*)d_in[2];  // [5, L]
    const int*   group  = (const int*)d_in[3];    // [B]
    const int*   labels = (const int*)d_in[4];    // [B]
    float* out = (float*)d_out;                   // [B, L]

    cudaFuncSetAttribute(gemm_fp8_kernel,
                         cudaFuncAttributeMaxDynamicSharedMemorySize, SMEM_TOTAL);

    prep_kernel<<<PREP_BLOCKS, 256>>>(hs, W, group, labels, out);

    dim3 grid(LL / TN, BB / TM, NHEAD);
    gemm_fp8_kernel<<<grid, NTHREADS, SMEM_TOTAL>>>(bias, out);
}

// round 14
// speedup vs baseline: 1.5904x; 1.5904x over previous
#include <cuda_runtime.h>
#include <cuda_fp16.h>
#include <cuda_fp8.h>
#include <stdint.h>

// ---------------- problem constants ----------------
#define BB 8192
#define HH 1024
#define LL 1024
#define NHEAD 5

// ---------------- GEMM config ----------------
#define TM 128
#define TN 128
#define KC 64            // K bytes per smem chunk
#define NC (HH / KC)     // 16 chunks
#define NSTAGE 5
#define NTHREADS 128     // 4 warps, 64x64 warp tiles

#define WSCALE 64.0f
#define INV_WSCALE (1.0f / 64.0f)

// smem: rowIdx (pad to 1K) then 5 stages of (A 8K | B 8K)
#define STAGE_BYTES (128 * 64 + 128 * 64)
#define SM_STAGE0 1024
#define SMEM_TOTAL (SM_STAGE0 + NSTAGE * STAGE_BYTES)

// prep kernel block ranges: block 0 = bucket; then A-convert; then W-convert
#define PREP_A_BLOCKS 1024                   // 8 warps/block -> 8192 rows
#define PREP_W_BLOCKS 1280                   // 5M elems / 16 / 256
#define PREP_BLOCKS (1 + PREP_A_BLOCKS + PREP_W_BLOCKS)

// ---------------- scratch ----------------
__device__ int g_cnt[8];
__device__ int g_rows[6 * BB];
__device__ uint8_t g_a8[(size_t)BB * HH];                // e4m3 hidden (natural order)
__device__ uint8_t g_w8[(size_t)NHEAD * LL * HH];        // e4m3 W * 64

// ---------------- PTX helpers ----------------
__device__ __forceinline__ uint32_t smem_u32(const void* p) {
    uint32_t a;
    asm("{ .reg .u64 t; cvta.to.shared.u64 t, %1; cvt.u32.u64 %0, t; }" : "=r"(a) : "l"(p));
    return a;
}
#define CP_ASYNC16(dst, src) \
    asm volatile("cp.async.cg.shared.global [%0], [%1], 16;" :: "r"(dst), "l"(src))
#define CP_COMMIT() asm volatile("cp.async.commit_group;" ::: "memory")
#define CP_WAIT3()  asm volatile("cp.async.wait_group 3;" ::: "memory")

// A fragment for m16n8k32 e4m3: lanes 0-15 rows (16B seg c16), lanes 16-31 seg c16+1.
__device__ __forceinline__ void ld_frag4a(uint32_t* f, uint32_t sbase, int rowbase,
                                          int c16, int lane) {
    int r = rowbase + (lane & 15);
    int cc = c16 + (lane >> 4);
    uint32_t addr = sbase + r * 64 + (((cc ^ ((r >> 1) & 3))) << 4);
    asm volatile("ldmatrix.sync.aligned.m8n8.x4.shared.b16 {%0,%1,%2,%3}, [%4];"
                 : "=r"(f[0]), "=r"(f[1]), "=r"(f[2]), "=r"(f[3]) : "r"(addr));
}

// B fragments for two n8 tiles at once.
__device__ __forceinline__ void ld_frag4b(uint32_t* f, uint32_t sbase, int rowbase,
                                          int c16, int lane) {
    int r = rowbase + (lane & 7) + ((lane >> 4) << 3);
    int cc = c16 + ((lane >> 3) & 1);
    uint32_t addr = sbase + r * 64 + (((cc ^ ((r >> 1) & 3))) << 4);
    asm volatile("ldmatrix.sync.aligned.m8n8.x4.shared.b16 {%0,%1,%2,%3}, [%4];"
                 : "=r"(f[0]), "=r"(f[1]), "=r"(f[2]), "=r"(f[3]) : "r"(addr));
}

__device__ __forceinline__ void mma16832(float* d, const uint32_t* a,
                                         uint32_t b0, uint32_t b1) {
    asm volatile(
        "mma.sync.aligned.m16n8k32.row.col.f32.e4m3.e4m3.f32 "
        "{%0,%1,%2,%3}, {%4,%5,%6,%7}, {%8,%9}, {%0,%1,%2,%3};"
        : "+f"(d[0]), "+f"(d[1]), "+f"(d[2]), "+f"(d[3])
        : "r"(a[0]), "r"(a[1]), "r"(a[2]), "r"(a[3]), "r"(b0), "r"(b1));
}

__device__ __forceinline__ uint8_t to_e4m3(float x) {
    return (uint8_t)__nv_cvt_float_to_fp8(x, __NV_SATFINITE, __NV_E4M3);
}
__device__ __forceinline__ uint32_t pack4_e4m3(float4 f) {
    return (uint32_t)to_e4m3(f.x) | ((uint32_t)to_e4m3(f.y) << 8) |
           ((uint32_t)to_e4m3(f.z) << 16) | ((uint32_t)to_e4m3(f.w) << 24);
}

// pack 6 group-counts into two u64 (groups 0-2 / 3-5, 21 bits each)
__device__ __forceinline__ void cnt_add(unsigned long long& c0, unsigned long long& c1,
                                        int g, unsigned long long v) {
    if (g < 3) c0 += v << (g * 21);
    else       c1 += v << ((g - 3) * 21);
}
__device__ __forceinline__ int cnt_get(unsigned long long c0, unsigned long long c1, int g) {
    unsigned long long c = (g < 3) ? c0 : c1;
    int s = ((g < 3) ? g : g - 3) * 21;
    return (int)((c >> s) & 0x1FFFFF);
}

// ---------------- fused prep ----------------
__global__ __launch_bounds__(256)
void prep_kernel(const float* __restrict__ hs, const float* __restrict__ W,
                 const int* __restrict__ group, const int* __restrict__ labels,
                 float* __restrict__ out) {
    const int bx = blockIdx.x;
    if (bx == 0) {
        __shared__ unsigned long long s0[256], s1[256];
        const int t = threadIdx.x;
        unsigned long long c0 = 0, c1 = 0;
        int gr[32];
#pragma unroll
        for (int i = 0; i < 32; i++) {
            int g = group[t * 32 + i];
            g = (g < 0) ? 0 : ((g > 5) ? 5 : g);
            gr[i] = g;
            cnt_add(c0, c1, g, 1ull);
        }
        s0[t] = c0; s1[t] = c1;
        __syncthreads();
        for (int off = 1; off < 256; off <<= 1) {
            unsigned long long a0 = (t >= off) ? s0[t - off] : 0ull;
            unsigned long long a1 = (t >= off) ? s1[t - off] : 0ull;
            __syncthreads();
            s0[t] += a0; s1[t] += a1;
            __syncthreads();
        }
        unsigned long long e0 = (t > 0) ? s0[t - 1] : 0ull;
        unsigned long long e1 = (t > 0) ? s1[t - 1] : 0ull;
        if (t < 6) g_cnt[t] = cnt_get(s0[255], s1[255], t);
        int base[6];
#pragma unroll
        for (int g = 0; g < 6; g++) base[g] = cnt_get(e0, e1, g);
#pragma unroll
        for (int i = 0; i < 32; i++) {
            int g = gr[i];
            g_rows[g * BB + base[g]] = t * 32 + i;
            base[g]++;
        }
    } else if (bx <= PREP_A_BLOCKS) {
        const int row = (bx - 1) * 8 + (threadIdx.x >> 5);
        const int lane = threadIdx.x & 31;
        int g = group[row];
        if (g < 0) g = 0;
        if (g > 5) g = 5;
        if (g == 5) {
            float v = (float)labels[row];
            float4 v4 = make_float4(v, v, v, v);
            float4* dp = reinterpret_cast<float4*>(out + (size_t)row * LL);
#pragma unroll
            for (int i = 0; i < 8; i++) dp[lane + i * 32] = v4;
        } else {
            const float4* src = reinterpret_cast<const float4*>(hs + (size_t)row * HH);
            uint32_t* dp = reinterpret_cast<uint32_t*>(g_a8 + (size_t)row * HH);
#pragma unroll
            for (int i = 0; i < 8; i++) dp[lane + i * 32] = pack4_e4m3(src[lane + i * 32]);
        }
    } else {
        const int i = (bx - 1 - PREP_A_BLOCKS) * 256 + threadIdx.x;   // 16-float group
        const float4* src = reinterpret_cast<const float4*>(W) + (size_t)i * 4;
        float4 f0 = src[0], f1 = src[1], f2 = src[2], f3 = src[3];
        f0.x *= WSCALE; f0.y *= WSCALE; f0.z *= WSCALE; f0.w *= WSCALE;
        f1.x *= WSCALE; f1.y *= WSCALE; f1.z *= WSCALE; f1.w *= WSCALE;
        f2.x *= WSCALE; f2.y *= WSCALE; f2.z *= WSCALE; f2.w *= WSCALE;
        f3.x *= WSCALE; f3.y *= WSCALE; f3.z *= WSCALE; f3.w *= WSCALE;
        uint4 o;
        o.x = pack4_e4m3(f0); o.y = pack4_e4m3(f1);
        o.z = pack4_e4m3(f2); o.w = pack4_e4m3(f3);
        reinterpret_cast<uint4*>(g_w8)[i] = o;
    }
}

// ---------------- FP8 MMA GEMM ----------------
// grid: (LL/TN=8, BB/TM=64, NHEAD). Early exit if row0 >= bucket count.
// 4 warps, 64x64 warp tiles, 5 stages, MMA-first / fill-after order.
__global__ __launch_bounds__(NTHREADS)
void gemm_fp8_kernel(const float* __restrict__ bias, float* __restrict__ out) {
    const int head = blockIdx.z;
    const int cnt = g_cnt[head];
    const int row0 = blockIdx.y * TM;
    if (row0 >= cnt) return;
    const int col0 = blockIdx.x * TN;

    extern __shared__ char smem[];
    const uint32_t sb = smem_u32(smem);
    int* rowIdx_s = reinterpret_cast<int*>(smem);

    const int tid = threadIdx.x;
    const int wid = tid >> 5;
    const int lid = tid & 31;
    const int WM = (wid & 1) * 64;       // 2 warp-rows of 64
    const int WN = (wid >> 1) * 64;      // 2 warp-cols of 64

    if (tid < TM) {
        int r = row0 + tid;
        rowIdx_s[tid] = (r < cnt) ? g_rows[head * BB + r] : -1;
    }
    __syncthreads();

    const uint8_t* __restrict__ bmat = g_w8 + ((size_t)head * LL + col0) * HH;

    // hoisted per-thread fill addressing: A gather pointers + fixed swizzled dsts
    const uint8_t* aptr[4];
    const uint8_t* bptr[4];
    uint32_t dofA[4], dofB[4];
#pragma unroll
    for (int l = 0; l < 4; l++) {
        const int q = l * NTHREADS + tid;          // 0..511
        const int r = q >> 2;
        const int seg = q & 3;
        int v = rowIdx_s[r];
        v = (v < 0) ? 0 : v;                       // clamp dead rows (masked at epilogue)
        aptr[l] = g_a8 + (size_t)v * HH + seg * 16;
        bptr[l] = bmat + (size_t)r * HH + seg * 16;
        dofA[l] = (uint32_t)(r * 64 + ((seg ^ ((r >> 1) & 3)) << 4));
        dofB[l] = (uint32_t)(8192 + r * 64 + ((seg ^ ((r >> 1) & 3)) << 4));
    }

    auto fill_stage = [&](int s, int chunk) {
        const int k0 = chunk * KC;
        const uint32_t sbase = sb + SM_STAGE0 + s * STAGE_BYTES;
#pragma unroll
        for (int l = 0; l < 4; l++) CP_ASYNC16(sbase + dofA[l], aptr[l] + k0);
#pragma unroll
        for (int l = 0; l < 4; l++) CP_ASYNC16(sbase + dofB[l], bptr[l] + k0);
    };

    // prologue: chunks 0..3
    fill_stage(0, 0); CP_COMMIT();
    fill_stage(1, 1); CP_COMMIT();
    fill_stage(2, 2); CP_COMMIT();
    fill_stage(3, 3); CP_COMMIT();

    float acc[4][8][4];
#pragma unroll
    for (int i = 0; i < 4; i++)
#pragma unroll
        for (int j = 0; j < 8; j++)
#pragma unroll
            for (int k = 0; k < 4; k++) acc[i][j][k] = 0.0f;

    for (int c = 0; c < NC; c++) {
        CP_WAIT3();                 // chunk c resident (<=3 newer groups in flight)
        __syncthreads();            // all warps past previous iter's reads

        const uint32_t sbase = sb + SM_STAGE0 + (c % NSTAGE) * STAGE_BYTES;
        const uint32_t sA = sbase;
        const uint32_t sB = sbase + 8192;

        // MMA FIRST: LDSM chain starts immediately; cp.async issue drains after
#pragma unroll
        for (int kt = 0; kt < 2; kt++) {     // two k32 halves of the 64B chunk
            const int c16 = kt * 2;
            uint32_t bfr[16];
#pragma unroll
            for (int nb = 0; nb < 4; nb++)
                ld_frag4b(bfr + nb * 4, sB, WN + nb * 16, c16, lid);
            uint32_t afr[16];
#pragma unroll
            for (int mt = 0; mt < 4; mt++)
                ld_frag4a(afr + mt * 4, sA, WM + mt * 16, c16, lid);
#pragma unroll
            for (int mt = 0; mt < 4; mt++)
#pragma unroll
                for (int nb = 0; nb < 4; nb++) {
                    mma16832(acc[mt][nb * 2 + 0], afr + mt * 4,
                             bfr[nb * 4 + 0], bfr[nb * 4 + 1]);
                    mma16832(acc[mt][nb * 2 + 1], afr + mt * 4,
                             bfr[nb * 4 + 2], bfr[nb * 4 + 3]);
                }
        }

        // fill stage (c+4)%5: consumed at iter c-1, all warps past it via the sync
        if (c + 4 < NC) fill_stage((c + 4) % NSTAGE, c + 4);
        CP_COMMIT();                // keep group count uniform
    }

    // ---------------- epilogue ----------------
    const int groupID = lid >> 2;
    const int tig = lid & 3;
    const float* brow = bias + head * LL;

#pragma unroll
    for (int mt = 0; mt < 4; mt++) {
        const int mlo = WM + mt * 16 + groupID;
        const int r1 = rowIdx_s[mlo];
        const int r2 = rowIdx_s[mlo + 8];
#pragma unroll
        for (int nt = 0; nt < 8; nt++) {
            const int gc = col0 + WN + nt * 8 + tig * 2;
            const float2 bs = *reinterpret_cast<const float2*>(brow + gc);
            if (r1 >= 0) {
                float2 v = make_float2(acc[mt][nt][0] * INV_WSCALE + bs.x,
                                       acc[mt][nt][1] * INV_WSCALE + bs.y);
                *reinterpret_cast<float2*>(out + (size_t)r1 * LL + gc) = v;
            }
            if (r2 >= 0) {
                float2 v = make_float2(acc[mt][nt][2] * INV_WSCALE + bs.x,
                                       acc[mt][nt][3] * INV_WSCALE + bs.y);
                *reinterpret_cast<float2*>(out + (size_t)r2 * LL + gc) = v;
            }
        }
    }
}

// ---------------- launch ----------------
extern "C" void kernel_launch(void* const* d_in, const int* in_sizes, int n_in,
                              void* d_out, int out_size) {
    const float* hs     = (const float*)d_in[0];  // [B, H]
    const float* W      = (const float*)d_in[1];  // [5, L, H]
    const float* bias   = (const float*)d_in[2];  // [5, L]
    const int*   group  = (const int*)d_in[3];    // [B]
    const int*   labels = (const int*)d_in[4];    // [B]
    float* out = (float*)d_out;                   // [B, L]

    cudaFuncSetAttribute(gemm_fp8_kernel,
                         cudaFuncAttributeMaxDynamicSharedMemorySize, SMEM_TOTAL);

    prep_kernel<<<PREP_BLOCKS, 256>>>(hs, W, group, labels, out);

    dim3 grid(LL / TN, BB / TM, NHEAD);
    gemm_fp8_kernel<<<grid, NTHREADS, SMEM_TOTAL>>>(bias, out);
}